// round 15
// baseline (speedup 1.0000x reference)
#include <cuda_runtime.h>

// Problem constants (fixed by the reference)
#define BATCH 16
#define CIN   128
#define COUT  128
#define Hh    224
#define Ww    224
#define W4    (Ww / 4)          // 56 float4 per row
#define PLANE  (Hh * Ww)        // 50176 floats per (b,c) plane
#define PLANE4 (PLANE / 4)      // 12544 float4 per plane

// Half-width TR=2 tiles: 2 output rows x 112 cols; region 4 rows x 30 float4
#define TR    2
#define RR    4                 // region rows
#define TC4   28                // output float4 cols per tile
#define RC4   30                // region float4 cols (1 float4 edge each side)
#define SROW  (RC4 * 4)         // smem row stride in floats (120)
#define NCORE (RR * RC4)        // 120 float4 region slots
#define NOUT  (TR * TC4)        // 56 float4 output slots
#define NT    64
#define NSTEPS (NOUT * COUT / NT)  // 112 store iterations per tile
#define NSTR  112               // row strips per image
#define NHALF 2                 // column halves
#define NTILES_TOT (BATCH * NSTR * NHALF)   // 3584 tiles
#define GRID  (148 * 16)        // 2368 persistent CTAs (one full resident set)

__global__ __launch_bounds__(NT) void fused_cross_conv(const float* __restrict__ x,
                                                       const float* __restrict__ bias,
                                                       float* __restrict__ out) {
    __shared__ float  Csh[RR * SROW];   // channel-sum region (4 x 30 float4)
    __shared__ float4 Rsh[NOUT];        // stencil results
    __shared__ int    Osh[NOUT];        // per-slot plane-relative float4 offset
    __shared__ float  sb[COUT];

    const int tid = threadIdx.x;
    sb[tid]      = bias[tid];
    sb[tid + NT] = bias[tid + NT];

    // Static per-tile thread-slot geometry (independent of which tile)
    int  si[2], sjr[2], csm[2];         // region row, region col4, smem offset
#pragma unroll
    for (int k = 0; k < 2; k++) {
        int s = tid + k * NT;
        if (s < NCORE) {
            si[k]  = s / RC4;           // region row 0..3
            sjr[k] = s - si[k] * RC4;   // region col4 0..29
            csm[k] = si[k] * SROW + sjr[k] * 4;
        } else {
            si[k] = -1; sjr[k] = 0; csm[k] = -1;
        }
    }

    // Persistent loop: tiles bid, bid + GRID
    for (int w = blockIdx.x; w < NTILES_TOT; w += GRID) {
        // tile decomposition: strip index fastest (adjacent bids share halo rows)
        const int b    = w / (NSTR * NHALF);
        const int rem  = w - b * (NSTR * NHALF);
        const int half = rem / NSTR;
        const int t    = rem - half * NSTR;
        const int r0   = t * TR;
        const int c04  = half * TC4;

        // ---------------- Phase 1: channel sum into smem ----------------
        int  coff[2];
        bool cval[2];
        float4 acc[2];
#pragma unroll
        for (int k = 0; k < 2; k++) {
            acc[k] = make_float4(0.f, 0.f, 0.f, 0.f);
            if (si[k] >= 0) {
                int gr  = r0 - 1 + si[k];
                int gc4 = c04 - 1 + sjr[k];
                cval[k] = (gr >= 0) && (gr < Hh) && (gc4 >= 0) && (gc4 < W4);
                coff[k] = gr * W4 + gc4;
            } else {
                cval[k] = false; coff[k] = 0;
            }
        }

        const float4* x4b = reinterpret_cast<const float4*>(x) + (size_t)b * CIN * PLANE4;

#pragma unroll 8
        for (int c = 0; c < CIN; c++) {
            const float4* base = x4b + (size_t)c * PLANE4;
#pragma unroll
            for (int k = 0; k < 2; k++) {
                if (cval[k]) {
                    float4 v = base[coff[k]];
                    acc[k].x += v.x; acc[k].y += v.y; acc[k].z += v.z; acc[k].w += v.w;
                }
            }
        }

#pragma unroll
        for (int k = 0; k < 2; k++) {
            if (csm[k] >= 0) {
                float4 a = cval[k] ? acc[k] : make_float4(0.f, 0.f, 0.f, 0.f);
                *reinterpret_cast<float4*>(Csh + csm[k]) = a;
            }
        }
        __syncthreads();

        // ------- Phase 2a: stencil into smem (56 slots, no boundary branches) ----
        if (tid < NOUT) {
            int ii = tid / TC4;         // 0..1
            int j  = tid - ii * TC4;    // local output col4 0..27
            int cb = (j + 1) * 4;

            const float* rowC = Csh + (ii + 1) * SROW;
            const float* rowU = rowC - SROW;
            const float* rowD = rowC + SROW;

            float lm = rowC[cb - 1];
            float rp = rowC[cb + 4];
            float v0 = rowC[cb + 0], v1 = rowC[cb + 1];
            float v2 = rowC[cb + 2], v3 = rowC[cb + 3];

            float4 r;
            r.x = rowU[cb + 0] + rowD[cb + 0] + lm + v1 + v0;
            r.y = rowU[cb + 1] + rowD[cb + 1] + v0 + v2 + v1;
            r.z = rowU[cb + 2] + rowD[cb + 2] + v1 + v3 + v2;
            r.w = rowU[cb + 3] + rowD[cb + 3] + v2 + rp + v3;

            Rsh[tid] = r;
            Osh[tid] = (r0 + ii) * W4 + c04 + j;
        }
        __syncthreads();

        // ------- Phase 2b: 64 threads stream the 56x128 (slot,channel) stores ----
        // Flat f = o*NOUT + slot = tid + k*NT; step 64 = NOUT + 8.
        {
            float4* out4b = reinterpret_cast<float4*>(out) + (size_t)b * COUT * PLANE4;
            int o    = tid / NOUT;      // 0 or 1
            int slot = tid - o * NOUT;

#pragma unroll 8
            for (int k = 0; k < NSTEPS; k++) {
                float4 r  = Rsh[slot];
                float  bo = sb[o];
                float4 v  = make_float4(r.x + bo, r.y + bo, r.z + bo, r.w + bo);
                __stcs(out4b + (size_t)o * PLANE4 + Osh[slot], v);
                o    += 1;              // f += NOUT
                slot += NT - NOUT;      // f += 8
                if (slot >= NOUT) { slot -= NOUT; o += 1; }
            }
        }
        __syncthreads();                // protect Csh/Rsh/Osh before next tile
    }
}

extern "C" void kernel_launch(void* const* d_in, const int* in_sizes, int n_in,
                              void* d_out, int out_size) {
    const float* x    = (const float*)d_in[0];   // [16,128,224,224] f32
    const float* bias = (const float*)d_in[2];   // [128] f32
    float* out = (float*)d_out;                  // [16,128,224,224] f32

    fused_cross_conv<<<GRID, NT>>>(x, bias, out);
}

// round 17
// speedup vs baseline: 1.1633x; 1.1633x over previous
#include <cuda_runtime.h>

// Problem constants (fixed by the reference)
#define BATCH 16
#define CIN   128
#define COUT  128
#define Hh    224
#define Ww    224
#define W4    (Ww / 4)          // 56 float4 per row
#define PLANE  (Hh * Ww)        // 50176 floats per (b,c) plane
#define PLANE4 (PLANE / 4)      // 12544 float4 per plane

// TR=2 full-width row strips (confirmed sweet spot)
#define TR   2
#define RR   (TR + 2)           // 4 region rows
#define SSTR (Ww + 4)           // smem row stride in floats (228)
#define NCORE (RR * W4)         // 224 float4 region slots
#define NOUT  (TR * W4)         // 112 float4 output slots
#define NT   128
#define NTILES (Hh / TR)        // 112 strips per image

__global__ __launch_bounds__(NT) void fused_cross_conv(const float* __restrict__ x,
                                                       const float* __restrict__ bias,
                                                       float* __restrict__ out) {
    __shared__ float  Csh[RR * SSTR];   // channel-sum region
    __shared__ float4 Rsh[NOUT];        // stencil results
    __shared__ int    Osh[NOUT];        // per-slot output float4 offset (plane-rel)
    __shared__ float  sb[COUT];

    const int tid = threadIdx.x;
    sb[tid] = bias[tid];                // NT == COUT == 128

    const int bx = blockIdx.x;
    const int b  = bx / NTILES;
    const int t  = bx - b * NTILES;
    const int r0 = t * TR;

    // ---------------- Phase 1: channel sum into smem (float4, coalesced) -------
    int  coff[2];
    bool cval[2];
    int  csm[2];
    float4 acc[2];
#pragma unroll
    for (int k = 0; k < 2; k++) {
        int s = tid + k * NT;
        acc[k] = make_float4(0.f, 0.f, 0.f, 0.f);
        if (s < NCORE) {
            int i  = s / W4;
            int j4 = s - i * W4;
            int gr = r0 - 1 + i;
            cval[k] = (gr >= 0) && (gr < Hh);
            coff[k] = gr * W4 + j4;
            csm[k]  = i * SSTR + 4 * j4;
        } else {
            cval[k] = false; coff[k] = 0; csm[k] = -1;
        }
    }

    const float4* x4b = reinterpret_cast<const float4*>(x) + (size_t)b * CIN * PLANE4;

#pragma unroll 8
    for (int c = 0; c < CIN; c++) {
        const float4* base = x4b + (size_t)c * PLANE4;
#pragma unroll
        for (int k = 0; k < 2; k++) {
            if (cval[k]) {
                float4 v = base[coff[k]];      // default caching: keep halo in L2
                acc[k].x += v.x; acc[k].y += v.y; acc[k].z += v.z; acc[k].w += v.w;
            }
        }
    }

#pragma unroll
    for (int k = 0; k < 2; k++) {
        if (csm[k] >= 0) {
            float4 a = cval[k] ? acc[k] : make_float4(0.f, 0.f, 0.f, 0.f);
            *reinterpret_cast<float4*>(Csh + csm[k]) = a;
        }
    }
    __syncthreads();

    // ---------------- Phase 2a: stencil into smem (112 threads) ----------------
    if (tid < NOUT) {
        int ii = tid / W4;                 // 0..1
        int j4 = tid - ii * W4;            // 0..55
        int i  = ii + 1;
        int cb = 4 * j4;

        const float* rowC = Csh + i * SSTR;
        const float* rowU = rowC - SSTR;
        const float* rowD = rowC + SSTR;

        float lm = (cb > 0)      ? rowC[cb - 1] : 0.f;
        float rp = (cb + 4 < Ww) ? rowC[cb + 4] : 0.f;
        float v0 = rowC[cb + 0], v1 = rowC[cb + 1];
        float v2 = rowC[cb + 2], v3 = rowC[cb + 3];

        float4 r;
        r.x = rowU[cb + 0] + rowD[cb + 0] + lm + v1 + v0;
        r.y = rowU[cb + 1] + rowD[cb + 1] + v0 + v2 + v1;
        r.z = rowU[cb + 2] + rowD[cb + 2] + v1 + v3 + v2;
        r.w = rowU[cb + 3] + rowD[cb + 3] + v2 + rp + v3;

        Rsh[tid] = r;
        Osh[tid] = (r0 + ii) * W4 + j4;    // plane-relative float4 offset
    }
    __syncthreads();

    // ------- Phase 2b: all 128 threads stream the 112x128 (slot,channel) stores -
    // Flat index f = o * NOUT + slot, f = tid + k*NT.
    // Per step: f += 128 = NOUT + 16  =>  o += 1 always, slot += 16 with carry.
    {
        float4* out4b = reinterpret_cast<float4*>(out) + (size_t)b * COUT * PLANE4;
        int o    = tid / NOUT;             // 0 or 1
        int slot = tid - o * NOUT;

#pragma unroll 8
        for (int k = 0; k < NOUT; k++) {   // 112 iterations: 14336 total / 128 thr
            float4 r  = Rsh[slot];
            float  bo = sb[o];
            float4 v  = make_float4(r.x + bo, r.y + bo, r.z + bo, r.w + bo);
            __stcs(out4b + (size_t)o * PLANE4 + Osh[slot], v);
            o    += 1;                     // f += NOUT
            slot += NT - NOUT;             // f += 16
            if (slot >= NOUT) { slot -= NOUT; o += 1; }
        }
    }
}

extern "C" void kernel_launch(void* const* d_in, const int* in_sizes, int n_in,
                              void* d_out, int out_size) {
    const float* x    = (const float*)d_in[0];   // [16,128,224,224] f32
    const float* bias = (const float*)d_in[2];   // [128] f32
    float* out = (float*)d_out;                  // [16,128,224,224] f32

    fused_cross_conv<<<BATCH * NTILES, NT>>>(x, bias, out);
}